// round 5
// baseline (speedup 1.0000x reference)
#include <cuda_runtime.h>
#include <cuda_bf16.h>
#include <cuda_fp16.h>
#include <cstdint>

#define NN 100000
#define EE 600000
#define DD 128

// Scratch (allocation-free: __device__ globals)
__device__ __half g_hs16[(size_t)NN * DD];  // (X @ W) * dinv[row], fp16
__device__ __half g_h1[(size_t)NN * DD];    // layer-1 output (post relu), fp16
__device__ float g_dinv[NN];
__device__ int   g_cnt[NN];                 // in-degree (excl self loop)
__device__ int   g_rowptr[NN];              // CSR row starts
__device__ int   g_fill[NN];                // fill cursors
__device__ int   g_srcidx[EE];              // CSR column (src) indices
__device__ int   g_is64;                    // edge_index dtype flag
__device__ uint4 g_Whi[2][2048];            // W hi bf16 [K=128][N=128] per layer
__device__ uint4 g_Wlo[2][2048];            // W lo bf16 per layer

// ---------------------------------------------------------------------------
__device__ __forceinline__ uint32_t smem_u32(const void* p) {
    uint32_t a;
    asm("{ .reg .u64 t; cvta.to.shared.u64 t, %1; cvt.u32.u64 %0, t; }"
        : "=r"(a) : "l"(p));
    return a;
}

#define LDMATRIX_X4(r0, r1, r2, r3, addr) \
    asm volatile("ldmatrix.sync.aligned.m8n8.x4.shared.b16 {%0,%1,%2,%3}, [%4];" \
                 : "=r"(r0), "=r"(r1), "=r"(r2), "=r"(r3) : "r"(addr))
#define LDMATRIX_X4_T(r0, r1, r2, r3, addr) \
    asm volatile("ldmatrix.sync.aligned.m8n8.x4.trans.shared.b16 {%0,%1,%2,%3}, [%4];" \
                 : "=r"(r0), "=r"(r1), "=r"(r2), "=r"(r3) : "r"(addr))
#define MMA_BF16(c, a, b) \
    asm volatile("mma.sync.aligned.m16n8k16.row.col.f32.bf16.bf16.f32 " \
                 "{%0,%1,%2,%3}, {%4,%5,%6,%7}, {%8,%9}, {%0,%1,%2,%3};" \
                 : "+f"((c)[0]), "+f"((c)[1]), "+f"((c)[2]), "+f"((c)[3]) \
                 : "r"((a)[0]), "r"((a)[1]), "r"((a)[2]), "r"((a)[3]), \
                   "r"((b)[0]), "r"((b)[1]))

__device__ __forceinline__ int load_edge(const void* ei, long long pos) {
    if (g_is64) return (int)((const long long*)ei)[pos];
    return ((const int*)ei)[pos];
}

// ---------------------------------------------------------------------------
// Fused: zero g_cnt (whole grid) + dtype detection (block 0).
__global__ __launch_bounds__(1024)
void detect_zero_kernel(const int* __restrict__ w) {
    int i = blockIdx.x * 1024 + threadIdx.x;
    if (i < NN) g_cnt[i] = 0;
    if (blockIdx.x == 0) {
        __shared__ int s_any;
        if (threadIdx.x == 0) s_any = 0;
        __syncthreads();
        int acc = 0;
        for (int k = threadIdx.x; k < 4096; k += 1024)
            acc |= w[2 * (k * 137) + 1];
        if (acc) atomicOr(&s_any, 1);
        __syncthreads();
        if (threadIdx.x == 0) g_is64 = (s_any == 0) ? 1 : 0;
    }
}

__global__ void hist_kernel(const void* __restrict__ ei) {
    int e = blockIdx.x * blockDim.x + threadIdx.x;
    if (e >= EE) return;
    int d = load_edge(ei, (long long)EE + e);
    atomicAdd(&g_cnt[d], 1);
}

// Single-block chunked exclusive scan over g_cnt; emits rowptr, fill, dinv.
__global__ __launch_bounds__(1024)
void scan_kernel() {
    __shared__ int s_warp[32];
    __shared__ int s_tot;
    __shared__ int s_carry;
    const int tid = threadIdx.x, lane = tid & 31, wid = tid >> 5;
    if (tid == 0) s_carry = 0;
    __syncthreads();

    for (int base = 0; base < NN; base += 4096) {
        const int i0 = base + tid * 4;
        int c0 = 0, c1 = 0, c2 = 0, c3 = 0;
        if (i0 + 3 < NN) {
            int4 v = *(const int4*)(g_cnt + i0);
            c0 = v.x; c1 = v.y; c2 = v.z; c3 = v.w;
        } else {
            if (i0 + 0 < NN) c0 = g_cnt[i0 + 0];
            if (i0 + 1 < NN) c1 = g_cnt[i0 + 1];
            if (i0 + 2 < NN) c2 = g_cnt[i0 + 2];
            if (i0 + 3 < NN) c3 = g_cnt[i0 + 3];
        }
        int tsum = c0 + c1 + c2 + c3;

        int incl = tsum;
        #pragma unroll
        for (int o = 1; o < 32; o <<= 1) {
            int n = __shfl_up_sync(0xffffffffu, incl, o);
            if (lane >= o) incl += n;
        }
        if (lane == 31) s_warp[wid] = incl;
        __syncthreads();                       // sync1
        if (wid == 0) {
            int v = s_warp[lane];
            int wi = v;
            #pragma unroll
            for (int o = 1; o < 32; o <<= 1) {
                int n = __shfl_up_sync(0xffffffffu, wi, o);
                if (lane >= o) wi += n;
            }
            s_warp[lane] = wi - v;             // exclusive warp offsets
            if (lane == 31) s_tot = wi;
        }
        __syncthreads();                       // sync2

        int off = s_carry + s_warp[wid] + (incl - tsum);
        int o0 = off, o1 = off + c0, o2 = o1 + c1, o3 = o2 + c2;
        if (i0 + 0 < NN) { g_rowptr[i0+0] = o0; g_fill[i0+0] = o0; g_dinv[i0+0] = rsqrtf((float)(c0 + 1)); }
        if (i0 + 1 < NN) { g_rowptr[i0+1] = o1; g_fill[i0+1] = o1; g_dinv[i0+1] = rsqrtf((float)(c1 + 1)); }
        if (i0 + 2 < NN) { g_rowptr[i0+2] = o2; g_fill[i0+2] = o2; g_dinv[i0+2] = rsqrtf((float)(c2 + 1)); }
        if (i0 + 3 < NN) { g_rowptr[i0+3] = o3; g_fill[i0+3] = o3; g_dinv[i0+3] = rsqrtf((float)(c3 + 1)); }
        __syncthreads();                       // sync3
        if (tid == 0) s_carry += s_tot;
        // next iteration's sync1/sync2 order the carry update before its readers
    }
}

__global__ void fill_kernel(const void* __restrict__ ei) {
    int e = blockIdx.x * blockDim.x + threadIdx.x;
    if (e >= EE) return;
    int s = load_edge(ei, e);
    int d = load_edge(ei, (long long)EE + e);
    int pos = atomicAdd(&g_fill[d], 1);
    g_srcidx[pos] = s;
}

// ---------------------------------------------------------------------------
// W prep for BOTH layers: split fp32 [K=128][N=128] into bf16 hi/lo images.
__global__ void wprep_kernel(const float* __restrict__ W1,
                             const float* __restrict__ W2) {
    int t = blockIdx.x * blockDim.x + threadIdx.x;   // 4096 threads
    if (t >= 4096) return;
    int set = t >> 11;
    int u   = t & 2047;                              // k = u>>4, nchunk = u&15
    const float* wp = (set ? W2 : W1) + (u >> 4) * DD + (u & 15) * 8;
    unsigned hi[8], lo[8];
    #pragma unroll
    for (int j = 0; j < 8; j++) {
        float x = wp[j];
        __nv_bfloat16 h = __float2bfloat16_rn(x);
        float rem = x - __bfloat162float(h);
        __nv_bfloat16 l = __float2bfloat16_rn(rem);
        hi[j] = (unsigned)__bfloat16_as_ushort(h);
        lo[j] = (unsigned)__bfloat16_as_ushort(l);
    }
    g_Whi[set][u] = make_uint4(hi[0] | (hi[1] << 16), hi[2] | (hi[3] << 16),
                               hi[4] | (hi[5] << 16), hi[6] | (hi[7] << 16));
    g_Wlo[set][u] = make_uint4(lo[0] | (lo[1] << 16), lo[2] | (lo[3] << 16),
                               lo[4] | (lo[5] << 16), lo[6] | (lo[7] << 16));
}

// ---------------------------------------------------------------------------
// mma.sync split-bf16 GEMM: per CTA 128x128 tile, K=128.
// LAYER 0: input = fp32 param X, weights set 0.
// LAYER 1: input = g_h1 (fp16), weights set 1.
// Output: g_hs16[r,:] = fp16( (row @ W) * dinv[r] ).
#define XSTR 136
#define SM_XLO 34816
#define SM_WHI 69632
#define SM_WLO 104448
#define GEMM_SMEM 139264

template <int LAYER>
__global__ __launch_bounds__(256, 1)
void gemm_bf16_kernel(const float* __restrict__ Xf) {
    extern __shared__ __align__(16) char sm[];
    const int tid  = threadIdx.x;
    const int warp = tid >> 5;
    const int lane = tid & 31;
    const int row0 = blockIdx.x * 128;

    // --- W images -> smem (padded rows) ---
    {
        #pragma unroll
        for (int i = 0; i < 8; i++) {
            int idx = tid + i * 256;
            int off = (idx >> 4) * (XSTR * 2) + (idx & 15) * 16;
            *(uint4*)(sm + SM_WHI + off) = g_Whi[LAYER][idx];
            *(uint4*)(sm + SM_WLO + off) = g_Wlo[LAYER][idx];
        }
    }
    // --- X tile: -> bf16 hi/lo, padded rows ---
    {
        int r = tid >> 1;
        int khalf = (tid & 1) * 64;
        bool valid = (row0 + r) < NN;
        #pragma unroll
        for (int kb = 0; kb < 8; kb++) {
            int k = khalf + kb * 8;
            float f[8];
            if (LAYER == 0) {
                const float4* xp = (const float4*)(Xf + (size_t)(row0 + r) * DD);
                float4 a = valid ? xp[k >> 2] : make_float4(0.f, 0.f, 0.f, 0.f);
                float4 b = valid ? xp[(k >> 2) + 1] : make_float4(0.f, 0.f, 0.f, 0.f);
                f[0]=a.x; f[1]=a.y; f[2]=a.z; f[3]=a.w;
                f[4]=b.x; f[5]=b.y; f[6]=b.z; f[7]=b.w;
            } else {
                const uint4* hp = (const uint4*)(g_h1 + (size_t)(row0 + r) * DD);
                uint4 u = valid ? hp[k >> 3] : make_uint4(0u, 0u, 0u, 0u);
                unsigned uu[4] = {u.x, u.y, u.z, u.w};
                #pragma unroll
                for (int q = 0; q < 4; q++) {
                    float2 p = __half22float2(*(__half2*)&uu[q]);
                    f[q * 2] = p.x; f[q * 2 + 1] = p.y;
                }
            }
            unsigned hi[8], lo[8];
            #pragma unroll
            for (int j = 0; j < 8; j++) {
                __nv_bfloat16 h = __float2bfloat16_rn(f[j]);
                float rem = f[j] - __bfloat162float(h);
                __nv_bfloat16 l = __float2bfloat16_rn(rem);
                hi[j] = (unsigned)__bfloat16_as_ushort(h);
                lo[j] = (unsigned)__bfloat16_as_ushort(l);
            }
            int off = r * (XSTR * 2) + k * 2;
            *(uint4*)(sm + off) =
                make_uint4(hi[0] | (hi[1] << 16), hi[2] | (hi[3] << 16),
                           hi[4] | (hi[5] << 16), hi[6] | (hi[7] << 16));
            *(uint4*)(sm + SM_XLO + off) =
                make_uint4(lo[0] | (lo[1] << 16), lo[2] | (lo[3] << 16),
                           lo[4] | (lo[5] << 16), lo[6] | (lo[7] << 16));
        }
    }
    __syncthreads();

    // --- warp tiling: 4x2 warps, each 32 rows x 64 cols ---
    const int m_base = (warp >> 1) * 32;
    const int n_base = (warp & 1) * 64;

    const uint32_t sbase = smem_u32(sm);
    const int a_row = (lane & 7) + ((lane >> 3) & 1) * 8;
    const int a_col = (lane >> 4) * 8;
    const int b_krow = (lane & 7) + ((lane >> 3) & 1) * 8;
    const int b_ncol = (lane >> 4) * 8;

    float acc[2][8][4];
    #pragma unroll
    for (int mt = 0; mt < 2; mt++)
        #pragma unroll
        for (int j = 0; j < 8; j++)
            #pragma unroll
            for (int q = 0; q < 4; q++) acc[mt][j][q] = 0.f;

    #pragma unroll 2
    for (int ks = 0; ks < 8; ks++) {
        const int k0 = ks * 16;
        uint32_t ahi[2][4], alo[2][4], bhi[8][2], blo[8][2];
        #pragma unroll
        for (int mt = 0; mt < 2; mt++) {
            uint32_t aoff = ((m_base + mt * 16 + a_row) * XSTR + k0 + a_col) * 2;
            LDMATRIX_X4(ahi[mt][0], ahi[mt][1], ahi[mt][2], ahi[mt][3], sbase + aoff);
            LDMATRIX_X4(alo[mt][0], alo[mt][1], alo[mt][2], alo[mt][3],
                        sbase + SM_XLO + aoff);
        }
        #pragma unroll
        for (int jp = 0; jp < 4; jp++) {
            uint32_t boff = ((k0 + b_krow) * XSTR + n_base + jp * 16 + b_ncol) * 2;
            LDMATRIX_X4_T(bhi[jp * 2][0], bhi[jp * 2][1],
                          bhi[jp * 2 + 1][0], bhi[jp * 2 + 1][1],
                          sbase + SM_WHI + boff);
            LDMATRIX_X4_T(blo[jp * 2][0], blo[jp * 2][1],
                          blo[jp * 2 + 1][0], blo[jp * 2 + 1][1],
                          sbase + SM_WLO + boff);
        }
        #pragma unroll
        for (int mt = 0; mt < 2; mt++)
            #pragma unroll
            for (int j = 0; j < 8; j++) {
                MMA_BF16(acc[mt][j], ahi[mt], bhi[j]);
                MMA_BF16(acc[mt][j], ahi[mt], blo[j]);
                MMA_BF16(acc[mt][j], alo[mt], bhi[j]);
            }
    }

    // --- epilogue: fp16 stores, dinv fused ---
    #pragma unroll
    for (int mt = 0; mt < 2; mt++) {
        int r0 = row0 + m_base + mt * 16 + (lane >> 2);
        int r1 = r0 + 8;
        float di0 = (r0 < NN) ? g_dinv[r0] : 0.f;
        float di1 = (r1 < NN) ? g_dinv[r1] : 0.f;
        #pragma unroll
        for (int j = 0; j < 8; j++) {
            int c = n_base + j * 8 + (lane & 3) * 2;
            if (r0 < NN)
                *(__half2*)(g_hs16 + (size_t)r0 * DD + c) =
                    __floats2half2_rn(acc[mt][j][0] * di0, acc[mt][j][1] * di0);
            if (r1 < NN)
                *(__half2*)(g_hs16 + (size_t)r1 * DD + c) =
                    __floats2half2_rn(acc[mt][j][2] * di1, acc[mt][j][3] * di1);
        }
    }
}

// ---------------------------------------------------------------------------
__device__ __forceinline__ float4 h8_to_f4(uint2 u) {
    float2 a = __half22float2(*(__half2*)&u.x);
    float2 b = __half22float2(*(__half2*)&u.y);
    return make_float4(a.x, a.y, b.x, b.y);
}

// Gather: one warp per dst node; lane covers 4 cols (8B fp16).
// MODE 0: relu, fp16 output to g_h1.   MODE 1: fp32 output to `out`.
template <int MODE>
__global__ __launch_bounds__(256)
void gather_kernel(const float* __restrict__ bvec, float* __restrict__ out) {
    const int w    = (blockIdx.x * blockDim.x + threadIdx.x) >> 5;
    const int lane = threadIdx.x & 31;
    if (w >= NN) return;

    const uint2* hs = (const uint2*)g_hs16;
    const int start = g_rowptr[w];
    const int n     = g_cnt[w];

    float4 acc = h8_to_f4(hs[(size_t)w * 32 + lane]);   // self loop

    int j = 0;
    for (; j + 4 <= n; j += 4) {
        int s0 = g_srcidx[start + j + 0];
        int s1 = g_srcidx[start + j + 1];
        int s2 = g_srcidx[start + j + 2];
        int s3 = g_srcidx[start + j + 3];
        float4 v0 = h8_to_f4(hs[(size_t)s0 * 32 + lane]);
        float4 v1 = h8_to_f4(hs[(size_t)s1 * 32 + lane]);
        float4 v2 = h8_to_f4(hs[(size_t)s2 * 32 + lane]);
        float4 v3 = h8_to_f4(hs[(size_t)s3 * 32 + lane]);
        acc.x += v0.x + v1.x + v2.x + v3.x;
        acc.y += v0.y + v1.y + v2.y + v3.y;
        acc.z += v0.z + v1.z + v2.z + v3.z;
        acc.w += v0.w + v1.w + v2.w + v3.w;
    }
    for (; j < n; j++) {
        int s = g_srcidx[start + j];
        float4 v = h8_to_f4(hs[(size_t)s * 32 + lane]);
        acc.x += v.x; acc.y += v.y; acc.z += v.z; acc.w += v.w;
    }

    const float di = g_dinv[w];
    const float4 b = ((const float4*)bvec)[lane];
    float4 r;
    r.x = acc.x * di + b.x;
    r.y = acc.y * di + b.y;
    r.z = acc.z * di + b.z;
    r.w = acc.w * di + b.w;
    if (MODE == 0) {
        r.x = fmaxf(r.x, 0.f);
        r.y = fmaxf(r.y, 0.f);
        r.z = fmaxf(r.z, 0.f);
        r.w = fmaxf(r.w, 0.f);
        __half2 p0 = __floats2half2_rn(r.x, r.y);
        __half2 p1 = __floats2half2_rn(r.z, r.w);
        uint2 u;
        u.x = *(unsigned*)&p0;
        u.y = *(unsigned*)&p1;
        ((uint2*)g_h1)[(size_t)w * 32 + lane] = u;
    } else {
        ((float4*)out)[(size_t)w * 32 + lane] = r;
    }
}

// ---------------------------------------------------------------------------
extern "C" void kernel_launch(void* const* d_in, const int* in_sizes, int n_in,
                              void* d_out, int out_size) {
    const float* x  = (const float*)d_in[0];
    const float* W1 = (const float*)d_in[1];
    const float* b1 = (const float*)d_in[2];
    const float* W2 = (const float*)d_in[3];
    const float* b2 = (const float*)d_in[4];
    const void*  ei = d_in[5];
    float* out = (float*)d_out;

    (void)in_sizes; (void)n_in; (void)out_size;

    cudaFuncSetAttribute(gemm_bf16_kernel<0>,
                         cudaFuncAttributeMaxDynamicSharedMemorySize, GEMM_SMEM);
    cudaFuncSetAttribute(gemm_bf16_kernel<1>,
                         cudaFuncAttributeMaxDynamicSharedMemorySize, GEMM_SMEM);

    const int GEMM_BLOCKS   = (NN + 127) / 128;     // 782
    const int GATHER_BLOCKS = (NN * 32 + 255) / 256;

    // CSR build (4 kernels)
    detect_zero_kernel<<<(NN + 1023) / 1024, 1024>>>((const int*)ei);
    hist_kernel<<<(EE + 255) / 256, 256>>>(ei);
    scan_kernel<<<1, 1024>>>();
    fill_kernel<<<(EE + 255) / 256, 256>>>(ei);

    // Weight prep for both layers (1 kernel)
    wprep_kernel<<<16, 256>>>(W1, W2);

    // Layer 1
    gemm_bf16_kernel<0><<<GEMM_BLOCKS, 256, GEMM_SMEM>>>(x);
    gather_kernel<0><<<GATHER_BLOCKS, 256>>>(b1, out);

    // Layer 2
    gemm_bf16_kernel<1><<<GEMM_BLOCKS, 256, GEMM_SMEM>>>(nullptr);
    gather_kernel<1><<<GATHER_BLOCKS, 256>>>(b2, out);
}

// round 6
// speedup vs baseline: 1.2844x; 1.2844x over previous
#include <cuda_runtime.h>
#include <cuda_bf16.h>
#include <cstdint>

#define NN 100000
#define EE 600000
#define DD 128

#define SCAN_CHUNK 1024
#define NBLK_SCAN ((NN + SCAN_CHUNK - 1) / SCAN_CHUNK)   // 98

// Scratch (allocation-free: __device__ globals)
__device__ float g_hs[(size_t)NN * DD];   // (X @ W) * dinv[row]
__device__ float g_dinv[NN];
__device__ int   g_cnt[NN];               // in-degree (excl self loop)
__device__ int   g_rowptr[NN];            // CSR row starts
__device__ int   g_fill[NN];              // fill cursors
__device__ int   g_srcidx[EE];            // CSR column (src) indices
__device__ int   g_bsums[NBLK_SCAN];
__device__ int   g_is64;                  // edge_index dtype flag
__device__ uint4 g_Whi[2][2048];          // W hi bf16 [K=128][N=128] per layer
__device__ uint4 g_Wlo[2][2048];          // W lo bf16 per layer

// ---------------------------------------------------------------------------
__device__ __forceinline__ uint32_t smem_u32(const void* p) {
    uint32_t a;
    asm("{ .reg .u64 t; cvta.to.shared.u64 t, %1; cvt.u32.u64 %0, t; }"
        : "=r"(a) : "l"(p));
    return a;
}

#define LDMATRIX_X4(r0, r1, r2, r3, addr) \
    asm volatile("ldmatrix.sync.aligned.m8n8.x4.shared.b16 {%0,%1,%2,%3}, [%4];" \
                 : "=r"(r0), "=r"(r1), "=r"(r2), "=r"(r3) : "r"(addr))
#define LDMATRIX_X4_T(r0, r1, r2, r3, addr) \
    asm volatile("ldmatrix.sync.aligned.m8n8.x4.trans.shared.b16 {%0,%1,%2,%3}, [%4];" \
                 : "=r"(r0), "=r"(r1), "=r"(r2), "=r"(r3) : "r"(addr))
#define MMA_BF16(c, a, b) \
    asm volatile("mma.sync.aligned.m16n8k16.row.col.f32.bf16.bf16.f32 " \
                 "{%0,%1,%2,%3}, {%4,%5,%6,%7}, {%8,%9}, {%0,%1,%2,%3};" \
                 : "+f"((c)[0]), "+f"((c)[1]), "+f"((c)[2]), "+f"((c)[3]) \
                 : "r"((a)[0]), "r"((a)[1]), "r"((a)[2]), "r"((a)[3]), \
                   "r"((b)[0]), "r"((b)[1]))

__device__ __forceinline__ int load_edge(const void* ei, long long pos) {
    if (g_is64) return (int)((const long long*)ei)[pos];
    return ((const int*)ei)[pos];
}

// ---------------------------------------------------------------------------
// Fused: zero g_cnt (whole grid) + dtype detection (block 0).
__global__ __launch_bounds__(1024)
void detect_zero_kernel(const int* __restrict__ w) {
    int i = blockIdx.x * 1024 + threadIdx.x;
    if (i < NN) g_cnt[i] = 0;
    if (blockIdx.x == 0) {
        __shared__ int s_any;
        if (threadIdx.x == 0) s_any = 0;
        __syncthreads();
        int acc = 0;
        for (int k = threadIdx.x; k < 4096; k += 1024)
            acc |= w[2 * (k * 137) + 1];
        if (acc) atomicOr(&s_any, 1);
        __syncthreads();
        if (threadIdx.x == 0) g_is64 = (s_any == 0) ? 1 : 0;
    }
}

__global__ void hist_kernel(const void* __restrict__ ei) {
    int e = blockIdx.x * blockDim.x + threadIdx.x;
    if (e >= EE) return;
    int d = load_edge(ei, (long long)EE + e);
    atomicAdd(&g_cnt[d], 1);
}

// Per-chunk exclusive scan (chunks of 1024 = 256 thr x 4), emits g_bsums.
__global__ __launch_bounds__(256)
void scan1_kernel() {
    __shared__ int s_warp[8];
    const int tid  = threadIdx.x;
    const int base = blockIdx.x * SCAN_CHUNK + tid * 4;

    int v0 = (base + 0 < NN) ? g_cnt[base + 0] : 0;
    int v1 = (base + 1 < NN) ? g_cnt[base + 1] : 0;
    int v2 = (base + 2 < NN) ? g_cnt[base + 2] : 0;
    int v3 = (base + 3 < NN) ? g_cnt[base + 3] : 0;
    int tsum = v0 + v1 + v2 + v3;

    int lane = tid & 31, wid = tid >> 5;
    int incl = tsum;
    #pragma unroll
    for (int o = 1; o < 32; o <<= 1) {
        int n = __shfl_up_sync(0xffffffffu, incl, o);
        if (lane >= o) incl += n;
    }
    if (lane == 31) s_warp[wid] = incl;
    __syncthreads();
    if (wid == 0) {
        int w = (lane < 8) ? s_warp[lane] : 0;
        int wi = w;
        #pragma unroll
        for (int o = 1; o < 8; o <<= 1) {
            int n = __shfl_up_sync(0xffffffffu, wi, o);
            if (lane >= o) wi += n;
        }
        if (lane < 8) s_warp[lane] = wi - w;
        if (lane == 7 && blockIdx.x < NBLK_SCAN) g_bsums[blockIdx.x] = wi;
    }
    __syncthreads();

    int off = s_warp[wid] + (incl - tsum);
    if (base + 0 < NN) g_rowptr[base + 0] = off;
    if (base + 1 < NN) g_rowptr[base + 1] = off + v0;
    if (base + 2 < NN) g_rowptr[base + 2] = off + v0 + v1;
    if (base + 3 < NN) g_rowptr[base + 3] = off + v0 + v1 + v2;
}

// Fused scan2+scan3: each 256-thread block lies inside ONE 1024-chunk, so it
// block-reduces bsums[0..chunk) itself, then finalizes rowptr/fill/dinv.
__global__ __launch_bounds__(256)
void scan23_kernel() {
    __shared__ int s_part[8];
    const int tid   = threadIdx.x;
    const int lane  = tid & 31, wid = tid >> 5;
    const int i     = blockIdx.x * 256 + tid;
    const int chunk = (blockIdx.x * 256) / SCAN_CHUNK;   // constant per block

    int partial = (tid < chunk) ? g_bsums[tid] : 0;      // chunk <= 97 < 256
    #pragma unroll
    for (int o = 16; o > 0; o >>= 1)
        partial += __shfl_down_sync(0xffffffffu, partial, o);
    if (lane == 0) s_part[wid] = partial;
    __syncthreads();
    int off = s_part[0] + s_part[1] + s_part[2] + s_part[3]
            + s_part[4] + s_part[5] + s_part[6] + s_part[7];

    if (i < NN) {
        int rp = g_rowptr[i] + off;
        g_rowptr[i] = rp;
        g_fill[i]   = rp;
        g_dinv[i]   = rsqrtf((float)(g_cnt[i] + 1));
    }
}

__global__ void fill_kernel(const void* __restrict__ ei) {
    int e = blockIdx.x * blockDim.x + threadIdx.x;
    if (e >= EE) return;
    int s = load_edge(ei, e);
    int d = load_edge(ei, (long long)EE + e);
    int pos = atomicAdd(&g_fill[d], 1);
    g_srcidx[pos] = s;
}

// ---------------------------------------------------------------------------
// W prep for BOTH layers: split fp32 [K=128][N=128] into bf16 hi/lo images.
__global__ void wprep_kernel(const float* __restrict__ W1,
                             const float* __restrict__ W2) {
    int t = blockIdx.x * blockDim.x + threadIdx.x;   // 4096 threads
    if (t >= 4096) return;
    int set = t >> 11;
    int u   = t & 2047;                              // k = u>>4, nchunk = u&15
    const float* wp = (set ? W2 : W1) + (u >> 4) * DD + (u & 15) * 8;
    unsigned hi[8], lo[8];
    #pragma unroll
    for (int j = 0; j < 8; j++) {
        float x = wp[j];
        __nv_bfloat16 h = __float2bfloat16_rn(x);
        float rem = x - __bfloat162float(h);
        __nv_bfloat16 l = __float2bfloat16_rn(rem);
        hi[j] = (unsigned)__bfloat16_as_ushort(h);
        lo[j] = (unsigned)__bfloat16_as_ushort(l);
    }
    g_Whi[set][u] = make_uint4(hi[0] | (hi[1] << 16), hi[2] | (hi[3] << 16),
                               hi[4] | (hi[5] << 16), hi[6] | (hi[7] << 16));
    g_Wlo[set][u] = make_uint4(lo[0] | (lo[1] << 16), lo[2] | (lo[3] << 16),
                               lo[4] | (lo[5] << 16), lo[6] | (lo[7] << 16));
}

// ---------------------------------------------------------------------------
// mma.sync split-bf16 GEMM: per CTA 128x128 tile, K=128 (R4-proven).
// g_hs[r,:] = (X[r,:] @ W[layer]) * g_dinv[r].
#define XSTR 136
#define SM_XLO 34816
#define SM_WHI 69632
#define SM_WLO 104448
#define GEMM_SMEM 139264

__global__ __launch_bounds__(256, 1)
void gemm_bf16_kernel(const float* __restrict__ X, int layer) {
    extern __shared__ __align__(16) char sm[];
    const int tid  = threadIdx.x;
    const int warp = tid >> 5;
    const int lane = tid & 31;
    const int row0 = blockIdx.x * 128;

    // --- W images -> smem (padded rows) ---
    {
        #pragma unroll
        for (int i = 0; i < 8; i++) {
            int idx = tid + i * 256;
            int off = (idx >> 4) * (XSTR * 2) + (idx & 15) * 16;
            *(uint4*)(sm + SM_WHI + off) = g_Whi[layer][idx];
            *(uint4*)(sm + SM_WLO + off) = g_Wlo[layer][idx];
        }
    }
    // --- X tile: fp32 -> bf16 hi/lo, padded rows ---
    {
        int r = tid >> 1;
        int khalf = (tid & 1) * 64;
        bool valid = (row0 + r) < NN;
        const float4* xp = (const float4*)(X + (size_t)(row0 + r) * DD);
        #pragma unroll
        for (int kb = 0; kb < 8; kb++) {
            int k = khalf + kb * 8;
            float4 a = valid ? xp[k >> 2] : make_float4(0.f, 0.f, 0.f, 0.f);
            float4 b = valid ? xp[(k >> 2) + 1] : make_float4(0.f, 0.f, 0.f, 0.f);
            float f[8] = {a.x, a.y, a.z, a.w, b.x, b.y, b.z, b.w};
            unsigned hi[8], lo[8];
            #pragma unroll
            for (int j = 0; j < 8; j++) {
                __nv_bfloat16 h = __float2bfloat16_rn(f[j]);
                float rem = f[j] - __bfloat162float(h);
                __nv_bfloat16 l = __float2bfloat16_rn(rem);
                hi[j] = (unsigned)__bfloat16_as_ushort(h);
                lo[j] = (unsigned)__bfloat16_as_ushort(l);
            }
            int off = r * (XSTR * 2) + k * 2;
            *(uint4*)(sm + off) =
                make_uint4(hi[0] | (hi[1] << 16), hi[2] | (hi[3] << 16),
                           hi[4] | (hi[5] << 16), hi[6] | (hi[7] << 16));
            *(uint4*)(sm + SM_XLO + off) =
                make_uint4(lo[0] | (lo[1] << 16), lo[2] | (lo[3] << 16),
                           lo[4] | (lo[5] << 16), lo[6] | (lo[7] << 16));
        }
    }
    __syncthreads();

    const int m_base = (warp >> 1) * 32;
    const int n_base = (warp & 1) * 64;

    const uint32_t sbase = smem_u32(sm);
    const int a_row = (lane & 7) + ((lane >> 3) & 1) * 8;
    const int a_col = (lane >> 4) * 8;
    const int b_krow = (lane & 7) + ((lane >> 3) & 1) * 8;
    const int b_ncol = (lane >> 4) * 8;

    float acc[2][8][4];
    #pragma unroll
    for (int mt = 0; mt < 2; mt++)
        #pragma unroll
        for (int j = 0; j < 8; j++)
            #pragma unroll
            for (int q = 0; q < 4; q++) acc[mt][j][q] = 0.f;

    #pragma unroll 2
    for (int ks = 0; ks < 8; ks++) {
        const int k0 = ks * 16;
        uint32_t ahi[2][4], alo[2][4], bhi[8][2], blo[8][2];
        #pragma unroll
        for (int mt = 0; mt < 2; mt++) {
            uint32_t aoff = ((m_base + mt * 16 + a_row) * XSTR + k0 + a_col) * 2;
            LDMATRIX_X4(ahi[mt][0], ahi[mt][1], ahi[mt][2], ahi[mt][3], sbase + aoff);
            LDMATRIX_X4(alo[mt][0], alo[mt][1], alo[mt][2], alo[mt][3],
                        sbase + SM_XLO + aoff);
        }
        #pragma unroll
        for (int jp = 0; jp < 4; jp++) {
            uint32_t boff = ((k0 + b_krow) * XSTR + n_base + jp * 16 + b_ncol) * 2;
            LDMATRIX_X4_T(bhi[jp * 2][0], bhi[jp * 2][1],
                          bhi[jp * 2 + 1][0], bhi[jp * 2 + 1][1],
                          sbase + SM_WHI + boff);
            LDMATRIX_X4_T(blo[jp * 2][0], blo[jp * 2][1],
                          blo[jp * 2 + 1][0], blo[jp * 2 + 1][1],
                          sbase + SM_WLO + boff);
        }
        #pragma unroll
        for (int mt = 0; mt < 2; mt++)
            #pragma unroll
            for (int j = 0; j < 8; j++) {
                MMA_BF16(acc[mt][j], ahi[mt], bhi[j]);
                MMA_BF16(acc[mt][j], ahi[mt], blo[j]);
                MMA_BF16(acc[mt][j], alo[mt], bhi[j]);
            }
    }

    // --- epilogue: direct float2 stores, dinv fused ---
    #pragma unroll
    for (int mt = 0; mt < 2; mt++) {
        int r0 = row0 + m_base + mt * 16 + (lane >> 2);
        int r1 = r0 + 8;
        float di0 = (r0 < NN) ? g_dinv[r0] : 0.f;
        float di1 = (r1 < NN) ? g_dinv[r1] : 0.f;
        #pragma unroll
        for (int j = 0; j < 8; j++) {
            int c = n_base + j * 8 + (lane & 3) * 2;
            if (r0 < NN)
                *(float2*)(g_hs + (size_t)r0 * DD + c) =
                    make_float2(acc[mt][j][0] * di0, acc[mt][j][1] * di0);
            if (r1 < NN)
                *(float2*)(g_hs + (size_t)r1 * DD + c) =
                    make_float2(acc[mt][j][2] * di1, acc[mt][j][3] * di1);
        }
    }
}

// ---------------------------------------------------------------------------
// Gather: one warp per dst node; register accumulation, fused bias/relu.
template <bool RELU>
__global__ __launch_bounds__(256)
void gather_kernel(const float* __restrict__ bvec, float* __restrict__ out) {
    const int w    = (blockIdx.x * blockDim.x + threadIdx.x) >> 5;
    const int lane = threadIdx.x & 31;
    if (w >= NN) return;

    const float4* hs4 = (const float4*)g_hs;
    const int start = g_rowptr[w];
    const int n     = g_cnt[w];

    float4 acc = hs4[(size_t)w * 32 + lane];   // self loop

    int j = 0;
    for (; j + 4 <= n; j += 4) {
        int s0 = g_srcidx[start + j + 0];
        int s1 = g_srcidx[start + j + 1];
        int s2 = g_srcidx[start + j + 2];
        int s3 = g_srcidx[start + j + 3];
        float4 v0 = hs4[(size_t)s0 * 32 + lane];
        float4 v1 = hs4[(size_t)s1 * 32 + lane];
        float4 v2 = hs4[(size_t)s2 * 32 + lane];
        float4 v3 = hs4[(size_t)s3 * 32 + lane];
        acc.x += v0.x + v1.x + v2.x + v3.x;
        acc.y += v0.y + v1.y + v2.y + v3.y;
        acc.z += v0.z + v1.z + v2.z + v3.z;
        acc.w += v0.w + v1.w + v2.w + v3.w;
    }
    for (; j < n; j++) {
        int s = g_srcidx[start + j];
        float4 v = hs4[(size_t)s * 32 + lane];
        acc.x += v.x; acc.y += v.y; acc.z += v.z; acc.w += v.w;
    }

    const float di = g_dinv[w];
    const float4 b = ((const float4*)bvec)[lane];
    float4 r;
    r.x = acc.x * di + b.x;
    r.y = acc.y * di + b.y;
    r.z = acc.z * di + b.z;
    r.w = acc.w * di + b.w;
    if (RELU) {
        r.x = fmaxf(r.x, 0.f);
        r.y = fmaxf(r.y, 0.f);
        r.z = fmaxf(r.z, 0.f);
        r.w = fmaxf(r.w, 0.f);
    }
    ((float4*)out)[(size_t)w * 32 + lane] = r;
}

// ---------------------------------------------------------------------------
extern "C" void kernel_launch(void* const* d_in, const int* in_sizes, int n_in,
                              void* d_out, int out_size) {
    const float* x  = (const float*)d_in[0];
    const float* W1 = (const float*)d_in[1];
    const float* b1 = (const float*)d_in[2];
    const float* W2 = (const float*)d_in[3];
    const float* b2 = (const float*)d_in[4];
    const void*  ei = d_in[5];
    float* out = (float*)d_out;

    (void)in_sizes; (void)n_in; (void)out_size;

    cudaFuncSetAttribute(gemm_bf16_kernel,
                         cudaFuncAttributeMaxDynamicSharedMemorySize, GEMM_SMEM);

    const int GEMM_BLOCKS   = (NN + 127) / 128;     // 782
    const int GATHER_BLOCKS = (NN * 32 + 255) / 256;

    // CSR build (5 kernels, all parallel-grid)
    detect_zero_kernel<<<(NN + 1023) / 1024, 1024>>>((const int*)ei);
    hist_kernel<<<(EE + 255) / 256, 256>>>(ei);
    scan1_kernel<<<NBLK_SCAN, 256>>>();
    scan23_kernel<<<(NN + 255) / 256, 256>>>();
    fill_kernel<<<(EE + 255) / 256, 256>>>(ei);

    // Weight prep for both layers (1 kernel)
    wprep_kernel<<<16, 256>>>(W1, W2);

    // Layer 1
    gemm_bf16_kernel<<<GEMM_BLOCKS, 256, GEMM_SMEM>>>(x, 0);
    gather_kernel<true><<<GATHER_BLOCKS, 256>>>(b1, out);

    // Layer 2 (reads layer-1 output from d_out, stream-ordered)
    gemm_bf16_kernel<<<GEMM_BLOCKS, 256, GEMM_SMEM>>>(out, 1);
    gather_kernel<false><<<GATHER_BLOCKS, 256>>>(b2, out);
}

// round 7
// speedup vs baseline: 1.3288x; 1.0345x over previous
#include <cuda_runtime.h>
#include <cuda_bf16.h>
#include <cstdint>

#define NN 100000
#define EE 600000
#define DD 128

#define SCAN_CHUNK 1024
#define NBLK_SCAN ((NN + SCAN_CHUNK - 1) / SCAN_CHUNK)   // 98

// Scratch (allocation-free: __device__ globals)
__device__ float g_hs[(size_t)NN * DD];   // X @ W (raw, no dinv)
__device__ float g_dinv[NN];
__device__ int   g_cnt[NN];               // in-degree (excl self loop)
__device__ int   g_rowptr[NN];            // CSR row starts
__device__ int   g_fill[NN];              // fill cursors
__device__ int   g_srcidx[EE];            // CSR column (src) indices
__device__ int   g_bsums[NBLK_SCAN];
__device__ int   g_is64;                  // edge_index dtype flag
__device__ uint4 g_Whi[2][2048];          // W hi bf16 [K=128][N=128] per layer
__device__ uint4 g_Wlo[2][2048];          // W lo bf16 per layer

// ---------------------------------------------------------------------------
__device__ __forceinline__ uint32_t smem_u32(const void* p) {
    uint32_t a;
    asm("{ .reg .u64 t; cvta.to.shared.u64 t, %1; cvt.u32.u64 %0, t; }"
        : "=r"(a) : "l"(p));
    return a;
}

#define LDMATRIX_X4(r0, r1, r2, r3, addr) \
    asm volatile("ldmatrix.sync.aligned.m8n8.x4.shared.b16 {%0,%1,%2,%3}, [%4];" \
                 : "=r"(r0), "=r"(r1), "=r"(r2), "=r"(r3) : "r"(addr))
#define LDMATRIX_X4_T(r0, r1, r2, r3, addr) \
    asm volatile("ldmatrix.sync.aligned.m8n8.x4.trans.shared.b16 {%0,%1,%2,%3}, [%4];" \
                 : "=r"(r0), "=r"(r1), "=r"(r2), "=r"(r3) : "r"(addr))
#define MMA_BF16(c, a, b) \
    asm volatile("mma.sync.aligned.m16n8k16.row.col.f32.bf16.bf16.f32 " \
                 "{%0,%1,%2,%3}, {%4,%5,%6,%7}, {%8,%9}, {%0,%1,%2,%3};" \
                 : "+f"((c)[0]), "+f"((c)[1]), "+f"((c)[2]), "+f"((c)[3]) \
                 : "r"((a)[0]), "r"((a)[1]), "r"((a)[2]), "r"((a)[3]), \
                   "r"((b)[0]), "r"((b)[1]))

__device__ __forceinline__ int load_edge(const void* ei, long long pos) {
    if (g_is64) return (int)((const long long*)ei)[pos];
    return ((const int*)ei)[pos];
}

// ---------------------------------------------------------------------------
// Fused: zero g_cnt (whole grid) + dtype detection (block 0).
__global__ __launch_bounds__(1024)
void detect_zero_kernel(const int* __restrict__ w) {
    int i = blockIdx.x * 1024 + threadIdx.x;
    if (i < NN) g_cnt[i] = 0;
    if (blockIdx.x == 0) {
        __shared__ int s_any;
        if (threadIdx.x == 0) s_any = 0;
        __syncthreads();
        int acc = 0;
        for (int k = threadIdx.x; k < 4096; k += 1024)
            acc |= w[2 * (k * 137) + 1];
        if (acc) atomicOr(&s_any, 1);
        __syncthreads();
        if (threadIdx.x == 0) g_is64 = (s_any == 0) ? 1 : 0;
    }
}

__global__ void hist_kernel(const void* __restrict__ ei) {
    int e = blockIdx.x * blockDim.x + threadIdx.x;
    if (e >= EE) return;
    int d = load_edge(ei, (long long)EE + e);
    atomicAdd(&g_cnt[d], 1);
}

// Per-chunk exclusive scan (chunks of 1024 = 256 thr x 4), emits g_bsums.
__global__ __launch_bounds__(256)
void scan1_kernel() {
    __shared__ int s_warp[8];
    const int tid  = threadIdx.x;
    const int base = blockIdx.x * SCAN_CHUNK + tid * 4;

    int v0 = (base + 0 < NN) ? g_cnt[base + 0] : 0;
    int v1 = (base + 1 < NN) ? g_cnt[base + 1] : 0;
    int v2 = (base + 2 < NN) ? g_cnt[base + 2] : 0;
    int v3 = (base + 3 < NN) ? g_cnt[base + 3] : 0;
    int tsum = v0 + v1 + v2 + v3;

    int lane = tid & 31, wid = tid >> 5;
    int incl = tsum;
    #pragma unroll
    for (int o = 1; o < 32; o <<= 1) {
        int n = __shfl_up_sync(0xffffffffu, incl, o);
        if (lane >= o) incl += n;
    }
    if (lane == 31) s_warp[wid] = incl;
    __syncthreads();
    if (wid == 0) {
        int w = (lane < 8) ? s_warp[lane] : 0;
        int wi = w;
        #pragma unroll
        for (int o = 1; o < 8; o <<= 1) {
            int n = __shfl_up_sync(0xffffffffu, wi, o);
            if (lane >= o) wi += n;
        }
        if (lane < 8) s_warp[lane] = wi - w;
        if (lane == 7 && blockIdx.x < NBLK_SCAN) g_bsums[blockIdx.x] = wi;
    }
    __syncthreads();

    int off = s_warp[wid] + (incl - tsum);
    if (base + 0 < NN) g_rowptr[base + 0] = off;
    if (base + 1 < NN) g_rowptr[base + 1] = off + v0;
    if (base + 2 < NN) g_rowptr[base + 2] = off + v0 + v1;
    if (base + 3 < NN) g_rowptr[base + 3] = off + v0 + v1 + v2;
}

// Fused scan2+scan3: block-reduce bsums below own chunk, finalize rowptr/fill/dinv.
__global__ __launch_bounds__(256)
void scan23_kernel() {
    __shared__ int s_part[8];
    const int tid   = threadIdx.x;
    const int lane  = tid & 31, wid = tid >> 5;
    const int i     = blockIdx.x * 256 + tid;
    const int chunk = (blockIdx.x * 256) / SCAN_CHUNK;   // constant per block

    int partial = (tid < chunk) ? g_bsums[tid] : 0;      // chunk <= 97 < 256
    #pragma unroll
    for (int o = 16; o > 0; o >>= 1)
        partial += __shfl_down_sync(0xffffffffu, partial, o);
    if (lane == 0) s_part[wid] = partial;
    __syncthreads();
    int off = s_part[0] + s_part[1] + s_part[2] + s_part[3]
            + s_part[4] + s_part[5] + s_part[6] + s_part[7];

    if (i < NN) {
        int rp = g_rowptr[i] + off;
        g_rowptr[i] = rp;
        g_fill[i]   = rp;
        g_dinv[i]   = rsqrtf((float)(g_cnt[i] + 1));
    }
}

__global__ void fill_kernel(const void* __restrict__ ei) {
    int e = blockIdx.x * blockDim.x + threadIdx.x;
    if (e >= EE) return;
    int s = load_edge(ei, e);
    int d = load_edge(ei, (long long)EE + e);
    int pos = atomicAdd(&g_fill[d], 1);
    g_srcidx[pos] = s;
}

// ---------------------------------------------------------------------------
// W prep for BOTH layers: split fp32 [K=128][N=128] into bf16 hi/lo images.
__global__ void wprep_kernel(const float* __restrict__ W1,
                             const float* __restrict__ W2) {
    int t = blockIdx.x * blockDim.x + threadIdx.x;   // 4096 threads
    if (t >= 4096) return;
    int set = t >> 11;
    int u   = t & 2047;                              // k = u>>4, nchunk = u&15
    const float* wp = (set ? W2 : W1) + (u >> 4) * DD + (u & 15) * 8;
    unsigned hi[8], lo[8];
    #pragma unroll
    for (int j = 0; j < 8; j++) {
        float x = wp[j];
        __nv_bfloat16 h = __float2bfloat16_rn(x);
        float rem = x - __bfloat162float(h);
        __nv_bfloat16 l = __float2bfloat16_rn(rem);
        hi[j] = (unsigned)__bfloat16_as_ushort(h);
        lo[j] = (unsigned)__bfloat16_as_ushort(l);
    }
    g_Whi[set][u] = make_uint4(hi[0] | (hi[1] << 16), hi[2] | (hi[3] << 16),
                               hi[4] | (hi[5] << 16), hi[6] | (hi[7] << 16));
    g_Wlo[set][u] = make_uint4(lo[0] | (lo[1] << 16), lo[2] | (lo[3] << 16),
                               lo[4] | (lo[5] << 16), lo[6] | (lo[7] << 16));
}

// ---------------------------------------------------------------------------
// mma.sync split-bf16 GEMM: per CTA 128x128 tile, K=128.
// g_hs[r,:] = X[r,:] @ W[layer]   (raw; dinv applied in gather)
#define XSTR 136
#define SM_XLO 34816
#define SM_WHI 69632
#define SM_WLO 104448
#define GEMM_SMEM 139264

__global__ __launch_bounds__(256, 1)
void gemm_bf16_kernel(const float* __restrict__ X, int layer) {
    extern __shared__ __align__(16) char sm[];
    const int tid  = threadIdx.x;
    const int warp = tid >> 5;
    const int lane = tid & 31;
    const int row0 = blockIdx.x * 128;

    // --- W images -> smem (padded rows) ---
    {
        #pragma unroll
        for (int i = 0; i < 8; i++) {
            int idx = tid + i * 256;
            int off = (idx >> 4) * (XSTR * 2) + (idx & 15) * 16;
            *(uint4*)(sm + SM_WHI + off) = g_Whi[layer][idx];
            *(uint4*)(sm + SM_WLO + off) = g_Wlo[layer][idx];
        }
    }
    // --- X tile: fp32 -> bf16 hi/lo, padded rows ---
    {
        int r = tid >> 1;
        int khalf = (tid & 1) * 64;
        bool valid = (row0 + r) < NN;
        const float4* xp = (const float4*)(X + (size_t)(row0 + r) * DD);
        #pragma unroll
        for (int kb = 0; kb < 8; kb++) {
            int k = khalf + kb * 8;
            float4 a = valid ? xp[k >> 2] : make_float4(0.f, 0.f, 0.f, 0.f);
            float4 b = valid ? xp[(k >> 2) + 1] : make_float4(0.f, 0.f, 0.f, 0.f);
            float f[8] = {a.x, a.y, a.z, a.w, b.x, b.y, b.z, b.w};
            unsigned hi[8], lo[8];
            #pragma unroll
            for (int j = 0; j < 8; j++) {
                __nv_bfloat16 h = __float2bfloat16_rn(f[j]);
                float rem = f[j] - __bfloat162float(h);
                __nv_bfloat16 l = __float2bfloat16_rn(rem);
                hi[j] = (unsigned)__bfloat16_as_ushort(h);
                lo[j] = (unsigned)__bfloat16_as_ushort(l);
            }
            int off = r * (XSTR * 2) + k * 2;
            *(uint4*)(sm + off) =
                make_uint4(hi[0] | (hi[1] << 16), hi[2] | (hi[3] << 16),
                           hi[4] | (hi[5] << 16), hi[6] | (hi[7] << 16));
            *(uint4*)(sm + SM_XLO + off) =
                make_uint4(lo[0] | (lo[1] << 16), lo[2] | (lo[3] << 16),
                           lo[4] | (lo[5] << 16), lo[6] | (lo[7] << 16));
        }
    }
    __syncthreads();

    const int m_base = (warp >> 1) * 32;
    const int n_base = (warp & 1) * 64;

    const uint32_t sbase = smem_u32(sm);
    const int a_row = (lane & 7) + ((lane >> 3) & 1) * 8;
    const int a_col = (lane >> 4) * 8;
    const int b_krow = (lane & 7) + ((lane >> 3) & 1) * 8;
    const int b_ncol = (lane >> 4) * 8;

    float acc[2][8][4];
    #pragma unroll
    for (int mt = 0; mt < 2; mt++)
        #pragma unroll
        for (int j = 0; j < 8; j++)
            #pragma unroll
            for (int q = 0; q < 4; q++) acc[mt][j][q] = 0.f;

    #pragma unroll 2
    for (int ks = 0; ks < 8; ks++) {
        const int k0 = ks * 16;
        uint32_t ahi[2][4], alo[2][4], bhi[8][2], blo[8][2];
        #pragma unroll
        for (int mt = 0; mt < 2; mt++) {
            uint32_t aoff = ((m_base + mt * 16 + a_row) * XSTR + k0 + a_col) * 2;
            LDMATRIX_X4(ahi[mt][0], ahi[mt][1], ahi[mt][2], ahi[mt][3], sbase + aoff);
            LDMATRIX_X4(alo[mt][0], alo[mt][1], alo[mt][2], alo[mt][3],
                        sbase + SM_XLO + aoff);
        }
        #pragma unroll
        for (int jp = 0; jp < 4; jp++) {
            uint32_t boff = ((k0 + b_krow) * XSTR + n_base + jp * 16 + b_ncol) * 2;
            LDMATRIX_X4_T(bhi[jp * 2][0], bhi[jp * 2][1],
                          bhi[jp * 2 + 1][0], bhi[jp * 2 + 1][1],
                          sbase + SM_WHI + boff);
            LDMATRIX_X4_T(blo[jp * 2][0], blo[jp * 2][1],
                          blo[jp * 2 + 1][0], blo[jp * 2 + 1][1],
                          sbase + SM_WLO + boff);
        }
        #pragma unroll
        for (int mt = 0; mt < 2; mt++)
            #pragma unroll
            for (int j = 0; j < 8; j++) {
                MMA_BF16(acc[mt][j], ahi[mt], bhi[j]);
                MMA_BF16(acc[mt][j], ahi[mt], blo[j]);
                MMA_BF16(acc[mt][j], alo[mt], bhi[j]);
            }
    }

    // --- epilogue: direct float2 stores (raw, no dinv) ---
    #pragma unroll
    for (int mt = 0; mt < 2; mt++) {
        int r0 = row0 + m_base + mt * 16 + (lane >> 2);
        int r1 = r0 + 8;
        #pragma unroll
        for (int j = 0; j < 8; j++) {
            int c = n_base + j * 8 + (lane & 3) * 2;
            if (r0 < NN)
                *(float2*)(g_hs + (size_t)r0 * DD + c) =
                    make_float2(acc[mt][j][0], acc[mt][j][1]);
            if (r1 < NN)
                *(float2*)(g_hs + (size_t)r1 * DD + c) =
                    make_float2(acc[mt][j][2], acc[mt][j][3]);
        }
    }
}

// ---------------------------------------------------------------------------
// Gather: one warp per dst node; per-edge dinv[src] FMA, fused bias/relu.
template <bool RELU>
__global__ __launch_bounds__(256)
void gather_kernel(const float* __restrict__ bvec, float* __restrict__ out) {
    const int w    = (blockIdx.x * blockDim.x + threadIdx.x) >> 5;
    const int lane = threadIdx.x & 31;
    if (w >= NN) return;

    const float4* hs4 = (const float4*)g_hs;
    const int start = g_rowptr[w];
    const int n     = g_cnt[w];
    const float di  = g_dinv[w];

    float4 sv = hs4[(size_t)w * 32 + lane];   // self loop: h[w]*dinv[w]
    float4 acc = make_float4(sv.x * di, sv.y * di, sv.z * di, sv.w * di);

    int j = 0;
    for (; j + 4 <= n; j += 4) {
        int s0 = g_srcidx[start + j + 0];
        int s1 = g_srcidx[start + j + 1];
        int s2 = g_srcidx[start + j + 2];
        int s3 = g_srcidx[start + j + 3];
        float d0 = g_dinv[s0], d1 = g_dinv[s1], d2 = g_dinv[s2], d3 = g_dinv[s3];
        float4 v0 = hs4[(size_t)s0 * 32 + lane];
        float4 v1 = hs4[(size_t)s1 * 32 + lane];
        float4 v2 = hs4[(size_t)s2 * 32 + lane];
        float4 v3 = hs4[(size_t)s3 * 32 + lane];
        acc.x = fmaf(v0.x, d0, fmaf(v1.x, d1, fmaf(v2.x, d2, fmaf(v3.x, d3, acc.x))));
        acc.y = fmaf(v0.y, d0, fmaf(v1.y, d1, fmaf(v2.y, d2, fmaf(v3.y, d3, acc.y))));
        acc.z = fmaf(v0.z, d0, fmaf(v1.z, d1, fmaf(v2.z, d2, fmaf(v3.z, d3, acc.z))));
        acc.w = fmaf(v0.w, d0, fmaf(v1.w, d1, fmaf(v2.w, d2, fmaf(v3.w, d3, acc.w))));
    }
    for (; j < n; j++) {
        int s = g_srcidx[start + j];
        float ds = g_dinv[s];
        float4 v = hs4[(size_t)s * 32 + lane];
        acc.x = fmaf(v.x, ds, acc.x);
        acc.y = fmaf(v.y, ds, acc.y);
        acc.z = fmaf(v.z, ds, acc.z);
        acc.w = fmaf(v.w, ds, acc.w);
    }

    const float4 b = ((const float4*)bvec)[lane];
    float4 r;
    r.x = acc.x * di + b.x;
    r.y = acc.y * di + b.y;
    r.z = acc.z * di + b.z;
    r.w = acc.w * di + b.w;
    if (RELU) {
        r.x = fmaxf(r.x, 0.f);
        r.y = fmaxf(r.y, 0.f);
        r.z = fmaxf(r.z, 0.f);
        r.w = fmaxf(r.w, 0.f);
    }
    ((float4*)out)[(size_t)w * 32 + lane] = r;
}

// ---------------------------------------------------------------------------
extern "C" void kernel_launch(void* const* d_in, const int* in_sizes, int n_in,
                              void* d_out, int out_size) {
    const float* x  = (const float*)d_in[0];
    const float* W1 = (const float*)d_in[1];
    const float* b1 = (const float*)d_in[2];
    const float* W2 = (const float*)d_in[3];
    const float* b2 = (const float*)d_in[4];
    const void*  ei = d_in[5];
    float* out = (float*)d_out;

    (void)in_sizes; (void)n_in; (void)out_size;

    cudaFuncSetAttribute(gemm_bf16_kernel,
                         cudaFuncAttributeMaxDynamicSharedMemorySize, GEMM_SMEM);

    const int GEMM_BLOCKS   = (NN + 127) / 128;     // 782
    const int GATHER_BLOCKS = (NN * 32 + 255) / 256;

    // Fork a side stream (capture-legal event fork/join from the default stream).
    cudaStream_t s2;
    cudaStreamCreateWithFlags(&s2, cudaStreamNonBlocking);
    cudaEvent_t evFork, evJoin;
    cudaEventCreateWithFlags(&evFork, cudaEventDisableTiming);
    cudaEventCreateWithFlags(&evJoin, cudaEventDisableTiming);

    cudaEventRecord(evFork, 0);
    cudaStreamWaitEvent(s2, evFork, 0);

    // Branch B (s2): weight prep + GEMM-1 (independent of CSR/dinv)
    wprep_kernel<<<16, 256, 0, s2>>>(W1, W2);
    gemm_bf16_kernel<<<GEMM_BLOCKS, 256, GEMM_SMEM, s2>>>(x, 0);

    // Branch A (default stream): CSR build
    detect_zero_kernel<<<(NN + 1023) / 1024, 1024>>>((const int*)ei);
    hist_kernel<<<(EE + 255) / 256, 256>>>(ei);
    scan1_kernel<<<NBLK_SCAN, 256>>>();
    scan23_kernel<<<(NN + 255) / 256, 256>>>();
    fill_kernel<<<(EE + 255) / 256, 256>>>(ei);

    // Join
    cudaEventRecord(evJoin, s2);
    cudaStreamWaitEvent(0, evJoin, 0);

    // Layer 1 aggregation, then layer 2 (sequential by data dependence)
    gather_kernel<true><<<GATHER_BLOCKS, 256>>>(b1, out);
    gemm_bf16_kernel<<<GEMM_BLOCKS, 256, GEMM_SMEM>>>(out, 1);
    gather_kernel<false><<<GATHER_BLOCKS, 256>>>(b2, out);

    cudaEventDestroy(evFork);
    cudaEventDestroy(evJoin);
}